// round 6
// baseline (speedup 1.0000x reference)
#include <cuda_runtime.h>
#include <cuda_bf16.h>
#include <cstdint>

#define GN 8192

// ---------------------------------------------------------------------------
// Device-global scratch (allocation-free per harness rules)
// ---------------------------------------------------------------------------
__device__ float g_dinv[GN];
__device__ __nv_bfloat16 g_adj_hi[(size_t)GN * GN];   // 128 MB
__device__ __nv_bfloat16 g_adj_lo[(size_t)GN * GN];   // 128 MB
// double-buffered per layer (ping-pong): fp32 Zs + transposed bf16 planes [n][k]
__device__ float g_Zs[2][(size_t)GN * 128];
__device__ __nv_bfloat16 g_Bhi[2][(size_t)128 * GN];
__device__ __nv_bfloat16 g_Blo[2][(size_t)128 * GN];

// ---------------------------------------------------------------------------
// PTX helpers (compute_103-safe: cp.async + ldmatrix + mma.sync only)
// ---------------------------------------------------------------------------
__device__ __forceinline__ uint32_t smem_u32(const void* p) {
    uint32_t a;
    asm("{ .reg .u64 t; cvta.to.shared.u64 t, %1; cvt.u32.u64 %0, t; }" : "=r"(a) : "l"(p));
    return a;
}
__device__ __forceinline__ void cp16(uint32_t dst, const void* src) {
    asm volatile("cp.async.cg.shared.global [%0], [%1], 16;" :: "r"(dst), "l"(src));
}
__device__ __forceinline__ void cp_commit() { asm volatile("cp.async.commit_group;" ::: "memory"); }
template<int N>
__device__ __forceinline__ void cp_wait() { asm volatile("cp.async.wait_group %0;" :: "n"(N) : "memory"); }

__device__ __forceinline__ void ldsm4(uint32_t* r, uint32_t addr) {
    asm volatile("ldmatrix.sync.aligned.m8n8.x4.shared.b16 {%0,%1,%2,%3}, [%4];"
                 : "=r"(r[0]), "=r"(r[1]), "=r"(r[2]), "=r"(r[3]) : "r"(addr));
}
__device__ __forceinline__ void mma_bf16(float* d, const uint32_t* a, const uint32_t* b) {
    asm volatile("mma.sync.aligned.m16n8k16.row.col.f32.bf16.bf16.f32 "
                 "{%0,%1,%2,%3}, {%4,%5,%6,%7}, {%8,%9}, {%0,%1,%2,%3};"
                 : "+f"(d[0]), "+f"(d[1]), "+f"(d[2]), "+f"(d[3])
                 : "r"(a[0]), "r"(a[1]), "r"(a[2]), "r"(a[3]), "r"(b[0]), "r"(b[1]));
}

// ---------------------------------------------------------------------------
// Kernel 1: rowsum + fp32 -> bf16 hi/lo split of adj (fused single pass)
// ---------------------------------------------------------------------------
__global__ void __launch_bounds__(256) convert_rowsum(const float* __restrict__ adj) {
    int row = blockIdx.x;
    int tid = threadIdx.x;
    const float4* src = reinterpret_cast<const float4*>(adj + (size_t)row * GN);
    uint2* dhi = reinterpret_cast<uint2*>(g_adj_hi + (size_t)row * GN);
    uint2* dlo = reinterpret_cast<uint2*>(g_adj_lo + (size_t)row * GN);
    float s = 0.f;
    for (int i = tid; i < GN / 4; i += 256) {
        float4 v = src[i];
        s += (v.x + v.y) + (v.z + v.w);
        __nv_bfloat16 h0 = __float2bfloat16(v.x);
        __nv_bfloat16 h1 = __float2bfloat16(v.y);
        __nv_bfloat16 h2 = __float2bfloat16(v.z);
        __nv_bfloat16 h3 = __float2bfloat16(v.w);
        __nv_bfloat16 l0 = __float2bfloat16(v.x - __bfloat162float(h0));
        __nv_bfloat16 l1 = __float2bfloat16(v.y - __bfloat162float(h1));
        __nv_bfloat16 l2 = __float2bfloat16(v.z - __bfloat162float(h2));
        __nv_bfloat16 l3 = __float2bfloat16(v.w - __bfloat162float(h3));
        uint2 hu, lu;
        hu.x = (uint32_t)__bfloat16_as_ushort(h0) | ((uint32_t)__bfloat16_as_ushort(h1) << 16);
        hu.y = (uint32_t)__bfloat16_as_ushort(h2) | ((uint32_t)__bfloat16_as_ushort(h3) << 16);
        lu.x = (uint32_t)__bfloat16_as_ushort(l0) | ((uint32_t)__bfloat16_as_ushort(l1) << 16);
        lu.y = (uint32_t)__bfloat16_as_ushort(l2) | ((uint32_t)__bfloat16_as_ushort(l3) << 16);
        dhi[i] = hu;
        dlo[i] = lu;
    }
    __shared__ float red[8];
    #pragma unroll
    for (int o = 16; o; o >>= 1) s += __shfl_down_sync(0xffffffffu, s, o);
    if ((tid & 31) == 0) red[tid >> 5] = s;
    __syncthreads();
    if (tid == 0) {
        float t = 0.f;
        #pragma unroll
        for (int w = 0; w < 8; w++) t += red[w];
        g_dinv[row] = rsqrtf(t + 1.0f);
    }
}

// ---------------------------------------------------------------------------
// Kernel 2 (layer 0 only): Zs = dinv ⊙ (x @ W0) -> buffer 0 (fp32 + bf16 planes)
// ---------------------------------------------------------------------------
template<int K, int NC>
__global__ void __launch_bounds__(256) feat_gemm(const float* __restrict__ Xin,
                                                 const float* __restrict__ W) {
    constexpr int CW = NC / 16;
    __shared__ float hs[64][K];
    __shared__ float ws[16][NC];
    int tid = threadIdx.x;
    int r0 = blockIdx.x * 64;
    int tx = tid & 15, ty = tid >> 4;

    {
        const float4* s4 = reinterpret_cast<const float4*>(Xin + (size_t)r0 * K);
        float4* d4 = reinterpret_cast<float4*>(&hs[0][0]);
        for (int i = tid; i < 64 * K / 4; i += 256) d4[i] = s4[i];
    }
    float acc[4][CW];
    #pragma unroll
    for (int r = 0; r < 4; r++)
        #pragma unroll
        for (int c = 0; c < CW; c++) acc[r][c] = 0.f;

    for (int kc = 0; kc < K / 16; kc++) {
        __syncthreads();
        {
            const float4* s4 = reinterpret_cast<const float4*>(W + kc * 16 * NC);
            float4* d4 = reinterpret_cast<float4*>(&ws[0][0]);
            for (int i = tid; i < 16 * NC / 4; i += 256) d4[i] = s4[i];
        }
        __syncthreads();
        #pragma unroll
        for (int k = 0; k < 16; k++) {
            float a0 = hs[ty * 4 + 0][kc * 16 + k];
            float a1 = hs[ty * 4 + 1][kc * 16 + k];
            float a2 = hs[ty * 4 + 2][kc * 16 + k];
            float a3 = hs[ty * 4 + 3][kc * 16 + k];
            #pragma unroll
            for (int c = 0; c < CW; c++) {
                float w = ws[k][c * 16 + tx];
                acc[0][c] = fmaf(a0, w, acc[0][c]);
                acc[1][c] = fmaf(a1, w, acc[1][c]);
                acc[2][c] = fmaf(a2, w, acc[2][c]);
                acc[3][c] = fmaf(a3, w, acc[3][c]);
            }
        }
    }
    #pragma unroll
    for (int r = 0; r < 4; r++) {
        int row = r0 + ty * 4 + r;
        float di = g_dinv[row];
        #pragma unroll
        for (int c = 0; c < CW; c++) {
            int col = c * 16 + tx;
            float z = di * acc[r][c];
            g_Zs[0][(size_t)row * NC + col] = z;
            __nv_bfloat16 h = __float2bfloat16(z);
            __nv_bfloat16 l = __float2bfloat16(z - __bfloat162float(h));
            g_Bhi[0][(size_t)col * GN + row] = h;
            g_Blo[0][(size_t)col * GN + row] = l;
        }
    }
}

// ---------------------------------------------------------------------------
// Kernel 3: split-precision HMMA SpMM + fused epilogue
//   h = [relu]( dinv[i]*( adj@Zs + Zs[i,:] ) + bias )
//   If NC>0: also computes next layer's Zs = dinv ⊙ (h @ W) in-kernel
//   (h stays in smem; next-layer planes written to buffer 1-SRC).
//   BM=64 (128 CTAs), 512 threads (16 warps, warp grid 4m x 4n), BK=32,
//   4-stage cp.async pipeline. Split accumulators: main (hi*hi) + corr.
// ---------------------------------------------------------------------------
template<int BN, int NC, int SRC, bool RELU>
__global__ void __launch_bounds__(512) spmm_hmma(const float* __restrict__ bias,
                                                 const float* __restrict__ Wn,
                                                 float* __restrict__ Out) {
    constexpr int BK = 32;
    constexpr int NT = GN / BK;               // 256 k-tiles
    constexpr int ASZ = 64 * BK * 2;          // 4 KB per A plane
    constexpr int BSZ = BN * BK * 2;          // per B plane
    constexpr int STAGE = 2 * ASZ + 2 * BSZ;
    constexpr int WN = BN / 4;                // warp n-extent
    constexpr int NF = WN / 8;                // n8 fragments per warp

    extern __shared__ char smem[];
    const uint32_t sb0 = smem_u32(smem);

    const int tid = threadIdx.x;
    const int lane = tid & 31;
    const int warp = tid >> 5;
    const int wm = warp >> 2;                 // 0..3 (16 rows each)
    const int wn = warp & 3;
    const int m0 = blockIdx.x * 64;
    const int n0c = wn * WN;

    float accM[NF][4], accC[NF][4];
    #pragma unroll
    for (int nf = 0; nf < NF; nf++)
        #pragma unroll
        for (int q = 0; q < 4; q++) { accM[nf][q] = 0.f; accC[nf][q] = 0.f; }

    auto issue = [&](int kt) {
        if (kt < NT) {
            const uint32_t sb = sb0 + (kt & 3) * STAGE;
            const int k0 = kt * BK;
            {   // A: 2 planes x 64 rows x 4 chunks = 512 -> 1 chunk/thread
                int plane = tid >> 8, cid = tid & 255;
                int row = cid >> 2, c = cid & 3;
                uint32_t so = row * 64 + ((c ^ ((row >> 1) & 3)) << 4);
                size_t go = (size_t)(m0 + row) * GN + k0 + c * 8;
                cp16(sb + plane * ASZ + so, (plane ? g_adj_lo : g_adj_hi) + go);
            }
            #pragma unroll
            for (int j = 0; j < BN / 64; j++) {  // B: 2 planes x BN rows x 4 chunks
                int idx = tid + j * 512;
                int plane = idx / (BN * 4), cid = idx % (BN * 4);
                int row = cid >> 2, c = cid & 3;
                uint32_t so = row * 64 + ((c ^ ((row >> 1) & 3)) << 4);
                size_t go = (size_t)row * GN + k0 + c * 8;
                cp16(sb + 2 * ASZ + plane * BSZ + so,
                     (plane ? g_Blo[SRC] : g_Bhi[SRC]) + go);
            }
        }
        cp_commit();
    };

    issue(0); issue(1); issue(2);

    #pragma unroll 1
    for (int kt = 0; kt < NT; kt++) {
        cp_wait<2>();
        __syncthreads();
        issue(kt + 3);            // refills slot (kt-1)&3, safe post-sync

        const uint32_t sb = sb0 + (kt & 3) * STAGE;
        #pragma unroll
        for (int ks = 0; ks < 2; ks++) {
            const int kc = ks * 2;
            uint32_t af[2][4];
            {
                int row = wm * 16 + (lane & 15);
                int ch = (kc + (lane >> 4)) ^ ((row >> 1) & 3);
                uint32_t ad = sb + row * 64 + ch * 16;
                ldsm4(af[0], ad);
                ldsm4(af[1], ad + ASZ);
            }
            uint32_t bf[2][NF][2];
            #pragma unroll
            for (int bt = 0; bt < NF / 2; bt++) {
                int row = n0c + bt * 16 + (lane & 7) + ((lane >> 4) << 3);
                int ch = (kc + ((lane >> 3) & 1)) ^ ((row >> 1) & 3);
                uint32_t ad = sb + 2 * ASZ + row * 64 + ch * 16;
                uint32_t t[4];
                ldsm4(t, ad);
                bf[0][2 * bt][0] = t[0]; bf[0][2 * bt][1] = t[1];
                bf[0][2 * bt + 1][0] = t[2]; bf[0][2 * bt + 1][1] = t[3];
                ldsm4(t, ad + BSZ);
                bf[1][2 * bt][0] = t[0]; bf[1][2 * bt][1] = t[1];
                bf[1][2 * bt + 1][0] = t[2]; bf[1][2 * bt + 1][1] = t[3];
            }
            #pragma unroll
            for (int nf = 0; nf < NF; nf++) {
                mma_bf16(accM[nf], af[0], bf[0][nf]);   // hi*hi -> main chain
                mma_bf16(accC[nf], af[0], bf[1][nf]);   // hi*lo -> corr chain
                mma_bf16(accC[nf], af[1], bf[0][nf]);   // lo*hi -> corr chain
            }
        }
    }
    __syncthreads();   // all warps done with stage smem before reuse

    // ---- epilogue: h = [relu](dinv*(acc + Zs_row) + bias) ----
    const int gr = lane >> 2;
    const int gc = (lane & 3) * 2;

    if constexpr (NC == 0) {
        // final layer: write Out directly
        #pragma unroll
        for (int half = 0; half < 2; half++) {
            int row = m0 + wm * 16 + half * 8 + gr;
            float di = g_dinv[row];
            #pragma unroll
            for (int nf = 0; nf < NF; nf++) {
                int col = n0c + nf * 8 + gc;
                float a0 = accM[nf][half * 2 + 0] + accC[nf][half * 2 + 0];
                float a1 = accM[nf][half * 2 + 1] + accC[nf][half * 2 + 1];
                float2 z = *reinterpret_cast<const float2*>(&g_Zs[SRC][(size_t)row * BN + col]);
                float v0 = fmaf(di, a0 + z.x, bias[col]);
                float v1 = fmaf(di, a1 + z.y, bias[col + 1]);
                if (RELU) { v0 = fmaxf(v0, 0.f); v1 = fmaxf(v1, 0.f); }
                *reinterpret_cast<float2*>(&Out[(size_t)row * BN + col]) = make_float2(v0, v1);
            }
        }
    } else {
        // fused feat-GEMM: hT[col][row] in smem (pad 66), W in smem, then h@W
        float* hT = reinterpret_cast<float*>(smem);          // [BN][66]
        float* Wsm = hT + BN * 66;                           // [BN][NC]
        #pragma unroll
        for (int half = 0; half < 2; half++) {
            int rl = wm * 16 + half * 8 + gr;
            int row = m0 + rl;
            float di = g_dinv[row];
            #pragma unroll
            for (int nf = 0; nf < NF; nf++) {
                int col = n0c + nf * 8 + gc;
                float a0 = accM[nf][half * 2 + 0] + accC[nf][half * 2 + 0];
                float a1 = accM[nf][half * 2 + 1] + accC[nf][half * 2 + 1];
                float2 z = *reinterpret_cast<const float2*>(&g_Zs[SRC][(size_t)row * BN + col]);
                float v0 = fmaf(di, a0 + z.x, bias[col]);
                float v1 = fmaf(di, a1 + z.y, bias[col + 1]);
                if (RELU) { v0 = fmaxf(v0, 0.f); v1 = fmaxf(v1, 0.f); }
                hT[col * 66 + rl] = v0;
                hT[(col + 1) * 66 + rl] = v1;
            }
        }
        // cooperative W load (L2-resident after first CTAs)
        #pragma unroll
        for (int it = 0; it < BN * NC / 4 / 512; it++) {
            int idx = tid + it * 512;
            reinterpret_cast<float4*>(Wsm)[idx] =
                reinterpret_cast<const float4*>(Wn)[idx];
        }
        __syncthreads();

        // Zs_next[row][j] = dinv[row] * sum_k h[row][k] * W[k][j]
        constexpr int CW = NC / 16;
        const int tx = tid & 15, ty = tid >> 4;   // 2 rows/thread, CW cols
        float a2[2][CW];
        #pragma unroll
        for (int r = 0; r < 2; r++)
            #pragma unroll
            for (int c = 0; c < CW; c++) a2[r][c] = 0.f;
        #pragma unroll 4
        for (int k = 0; k < BN; k++) {
            float h0 = hT[k * 66 + 2 * ty];
            float h1 = hT[k * 66 + 2 * ty + 1];
            #pragma unroll
            for (int c = 0; c < CW; c++) {
                float w = Wsm[k * NC + c * 16 + tx];
                a2[0][c] = fmaf(h0, w, a2[0][c]);
                a2[1][c] = fmaf(h1, w, a2[1][c]);
            }
        }
        constexpr int DST = 1 - SRC;
        #pragma unroll
        for (int r = 0; r < 2; r++) {
            int row = m0 + 2 * ty + r;
            float di = g_dinv[row];
            #pragma unroll
            for (int c = 0; c < CW; c++) {
                int col = c * 16 + tx;
                float z = di * a2[r][c];
                g_Zs[DST][(size_t)row * NC + col] = z;
                __nv_bfloat16 h = __float2bfloat16(z);
                __nv_bfloat16 l = __float2bfloat16(z - __bfloat162float(h));
                g_Bhi[DST][(size_t)col * GN + row] = h;
                g_Blo[DST][(size_t)col * GN + row] = l;
            }
        }
    }
}

// ---------------------------------------------------------------------------
// Launch: 3-layer GCN
// ---------------------------------------------------------------------------
extern "C" void kernel_launch(void* const* d_in, const int* in_sizes, int n_in,
                              void* d_out, int out_size) {
    const float* x   = (const float*)d_in[0];
    const float* adj = (const float*)d_in[1];
    const float* W0  = (const float*)d_in[2];
    const float* b0  = (const float*)d_in[3];
    const float* W1  = (const float*)d_in[4];
    const float* b1  = (const float*)d_in[5];
    const float* W2  = (const float*)d_in[6];
    const float* b2  = (const float*)d_in[7];
    float* out = (float*)d_out;

    // smem: max(mainloop stages, fused epilogue hT + W)
    const int MAIN128 = 4 * (2 * 4096 + 2 * 128 * 64);           // 98304
    const int MAIN64  = 4 * (2 * 4096 + 2 * 64 * 64);            // 65536
    const int SM_L1 = (MAIN128 > 128 * 66 * 4 + 128 * 128 * 4)
                    ? MAIN128 : (128 * 66 * 4 + 128 * 128 * 4);  // 99328
    const int SM_L2 = (MAIN128 > 128 * 66 * 4 + 128 * 64 * 4)
                    ? MAIN128 : (128 * 66 * 4 + 128 * 64 * 4);   // 98304
    const int SM_L3 = MAIN64;                                    // 65536
    cudaFuncSetAttribute(spmm_hmma<128, 128, 0, true>,
                         cudaFuncAttributeMaxDynamicSharedMemorySize, SM_L1);
    cudaFuncSetAttribute(spmm_hmma<128, 64, 1, true>,
                         cudaFuncAttributeMaxDynamicSharedMemorySize, SM_L2);
    cudaFuncSetAttribute(spmm_hmma<64, 0, 0, false>,
                         cudaFuncAttributeMaxDynamicSharedMemorySize, SM_L3);

    convert_rowsum<<<GN, 256>>>(adj);

    // layer 0 feat: Zs1 = dinv ⊙ (x@W0)  -> buffer 0
    feat_gemm<64, 128><<<GN / 64, 256>>>(x, W0);

    // layer 1: h1 = relu(An@Zs1 + b0); fused: Zs2 = dinv ⊙ (h1@W1) -> buffer 1
    spmm_hmma<128, 128, 0, true><<<GN / 64, 512, SM_L1>>>(b0, W1, nullptr);

    // layer 2: h2 = relu(An@Zs2 + b1); fused: Zs3 = dinv ⊙ (h2@W2) -> buffer 0
    spmm_hmma<128, 64, 1, true><<<GN / 64, 512, SM_L2>>>(b1, W2, nullptr);

    // layer 3: out = An@Zs3 + b2
    spmm_hmma<64, 0, 0, false><<<GN / 64, 512, SM_L3>>>(b2, nullptr, out);
}

// round 7
// speedup vs baseline: 1.3921x; 1.3921x over previous
#include <cuda_runtime.h>
#include <cuda_fp16.h>
#include <cstdint>

#define GN 8192

// ---------------------------------------------------------------------------
// Device-global scratch (allocation-free per harness rules)
// ---------------------------------------------------------------------------
__device__ float g_dinv[GN];
__device__ __half g_adj_h[(size_t)GN * GN];           // fp16 adj, 128 MB (single plane)
// double-buffered per layer (ping-pong): fp32 Zs + transposed fp16 planes [n][k]
__device__ float g_Zs[2][(size_t)GN * 128];
__device__ __half g_Bhi[2][(size_t)128 * GN];
__device__ __half g_Blo[2][(size_t)128 * GN];

// ---------------------------------------------------------------------------
// PTX helpers (compute_103-safe: cp.async + ldmatrix + mma.sync only)
// ---------------------------------------------------------------------------
__device__ __forceinline__ uint32_t smem_u32(const void* p) {
    uint32_t a;
    asm("{ .reg .u64 t; cvta.to.shared.u64 t, %1; cvt.u32.u64 %0, t; }" : "=r"(a) : "l"(p));
    return a;
}
__device__ __forceinline__ void cp16(uint32_t dst, const void* src) {
    asm volatile("cp.async.cg.shared.global [%0], [%1], 16;" :: "r"(dst), "l"(src));
}
__device__ __forceinline__ void cp_commit() { asm volatile("cp.async.commit_group;" ::: "memory"); }
template<int N>
__device__ __forceinline__ void cp_wait() { asm volatile("cp.async.wait_group %0;" :: "n"(N) : "memory"); }

__device__ __forceinline__ void ldsm4(uint32_t* r, uint32_t addr) {
    asm volatile("ldmatrix.sync.aligned.m8n8.x4.shared.b16 {%0,%1,%2,%3}, [%4];"
                 : "=r"(r[0]), "=r"(r[1]), "=r"(r[2]), "=r"(r[3]) : "r"(addr));
}
__device__ __forceinline__ void mma_f16(float* d, const uint32_t* a, const uint32_t* b) {
    asm volatile("mma.sync.aligned.m16n8k16.row.col.f32.f16.f16.f32 "
                 "{%0,%1,%2,%3}, {%4,%5,%6,%7}, {%8,%9}, {%0,%1,%2,%3};"
                 : "+f"(d[0]), "+f"(d[1]), "+f"(d[2]), "+f"(d[3])
                 : "r"(a[0]), "r"(a[1]), "r"(a[2]), "r"(a[3]), "r"(b[0]), "r"(b[1]));
}

// ---------------------------------------------------------------------------
// Kernel 1: rowsum (fp32-exact) + fp32 -> fp16 convert of adj (fused one pass)
// ---------------------------------------------------------------------------
__global__ void __launch_bounds__(256) convert_rowsum(const float* __restrict__ adj) {
    int row = blockIdx.x;
    int tid = threadIdx.x;
    const float4* src = reinterpret_cast<const float4*>(adj + (size_t)row * GN);
    uint2* dst = reinterpret_cast<uint2*>(g_adj_h + (size_t)row * GN);
    float s = 0.f;
    for (int i = tid; i < GN / 4; i += 256) {
        float4 v = src[i];
        s += (v.x + v.y) + (v.z + v.w);
        __half2 p0 = __floats2half2_rn(v.x, v.y);
        __half2 p1 = __floats2half2_rn(v.z, v.w);
        uint2 u;
        u.x = *reinterpret_cast<uint32_t*>(&p0);
        u.y = *reinterpret_cast<uint32_t*>(&p1);
        dst[i] = u;
    }
    __shared__ float red[8];
    #pragma unroll
    for (int o = 16; o; o >>= 1) s += __shfl_down_sync(0xffffffffu, s, o);
    if ((tid & 31) == 0) red[tid >> 5] = s;
    __syncthreads();
    if (tid == 0) {
        float t = 0.f;
        #pragma unroll
        for (int w = 0; w < 8; w++) t += red[w];
        g_dinv[row] = rsqrtf(t + 1.0f);
    }
}

// ---------------------------------------------------------------------------
// Kernel 2 (layer 0 only): Zs = dinv ⊙ (x @ W0) -> buffer 0 (fp32 + fp16 planes)
// ---------------------------------------------------------------------------
template<int K, int NC>
__global__ void __launch_bounds__(256) feat_gemm(const float* __restrict__ Xin,
                                                 const float* __restrict__ W) {
    constexpr int CW = NC / 16;
    __shared__ float hs[64][K];
    __shared__ float ws[16][NC];
    int tid = threadIdx.x;
    int r0 = blockIdx.x * 64;
    int tx = tid & 15, ty = tid >> 4;

    {
        const float4* s4 = reinterpret_cast<const float4*>(Xin + (size_t)r0 * K);
        float4* d4 = reinterpret_cast<float4*>(&hs[0][0]);
        for (int i = tid; i < 64 * K / 4; i += 256) d4[i] = s4[i];
    }
    float acc[4][CW];
    #pragma unroll
    for (int r = 0; r < 4; r++)
        #pragma unroll
        for (int c = 0; c < CW; c++) acc[r][c] = 0.f;

    for (int kc = 0; kc < K / 16; kc++) {
        __syncthreads();
        {
            const float4* s4 = reinterpret_cast<const float4*>(W + kc * 16 * NC);
            float4* d4 = reinterpret_cast<float4*>(&ws[0][0]);
            for (int i = tid; i < 16 * NC / 4; i += 256) d4[i] = s4[i];
        }
        __syncthreads();
        #pragma unroll
        for (int k = 0; k < 16; k++) {
            float a0 = hs[ty * 4 + 0][kc * 16 + k];
            float a1 = hs[ty * 4 + 1][kc * 16 + k];
            float a2 = hs[ty * 4 + 2][kc * 16 + k];
            float a3 = hs[ty * 4 + 3][kc * 16 + k];
            #pragma unroll
            for (int c = 0; c < CW; c++) {
                float w = ws[k][c * 16 + tx];
                acc[0][c] = fmaf(a0, w, acc[0][c]);
                acc[1][c] = fmaf(a1, w, acc[1][c]);
                acc[2][c] = fmaf(a2, w, acc[2][c]);
                acc[3][c] = fmaf(a3, w, acc[3][c]);
            }
        }
    }
    #pragma unroll
    for (int r = 0; r < 4; r++) {
        int row = r0 + ty * 4 + r;
        float di = g_dinv[row];
        #pragma unroll
        for (int c = 0; c < CW; c++) {
            int col = c * 16 + tx;
            float z = di * acc[r][c];
            g_Zs[0][(size_t)row * NC + col] = z;
            __half h = __float2half_rn(z);
            __half l = __float2half_rn(z - __half2float(h));
            g_Bhi[0][(size_t)col * GN + row] = h;
            g_Blo[0][(size_t)col * GN + row] = l;
        }
    }
}

// ---------------------------------------------------------------------------
// Kernel 3: fp16 2-pass HMMA SpMM + fused epilogue
//   acc = Ah@Bhi (main chain) + Ah@Blo (corr chain); A-quant error ~2e-4 ok.
//   h = [relu]( dinv[i]*( acc + Zs[i,:] ) + bias )
//   If NC>0: also computes next layer's Zs = dinv ⊙ (h @ W) in-kernel.
//   BM=64 (128 CTAs), 512 threads (16 warps, 4m x 4n), BK=64, 4-stage cp.async.
//   smem rows are 128B (8 chunks); swizzle: chunk' = c ^ (row & 7).
// ---------------------------------------------------------------------------
template<int BN, int NC, int SRC, bool RELU>
__global__ void __launch_bounds__(512) spmm_hmma(const float* __restrict__ bias,
                                                 const float* __restrict__ Wn,
                                                 float* __restrict__ Out) {
    constexpr int BK = 64;
    constexpr int NT = GN / BK;               // 128 k-tiles
    constexpr int ASZ = 64 * BK * 2;          // 8 KB (single fp16 A plane)
    constexpr int BSZ = BN * BK * 2;          // per B plane
    constexpr int STAGE = ASZ + 2 * BSZ;
    constexpr int WN = BN / 4;                // warp n-extent
    constexpr int NF = WN / 8;                // n8 fragments per warp

    extern __shared__ char smem[];
    const uint32_t sb0 = smem_u32(smem);

    const int tid = threadIdx.x;
    const int lane = tid & 31;
    const int warp = tid >> 5;
    const int wm = warp >> 2;                 // 0..3 (16 rows each)
    const int wn = warp & 3;
    const int m0 = blockIdx.x * 64;
    const int n0c = wn * WN;

    float accM[NF][4], accC[NF][4];
    #pragma unroll
    for (int nf = 0; nf < NF; nf++)
        #pragma unroll
        for (int q = 0; q < 4; q++) { accM[nf][q] = 0.f; accC[nf][q] = 0.f; }

    auto issue = [&](int kt) {
        if (kt < NT) {
            const uint32_t sb = sb0 + (kt & 3) * STAGE;
            const int k0 = kt * BK;
            {   // A: 64 rows x 8 chunks = 512 -> 1 chunk/thread
                int row = tid >> 3, c = tid & 7;
                uint32_t so = row * 128 + ((c ^ (row & 7)) << 4);
                cp16(sb + so, g_adj_h + (size_t)(m0 + row) * GN + k0 + c * 8);
            }
            #pragma unroll
            for (int j = 0; j < BN / 32; j++) {  // B: 2 planes x BN rows x 8 chunks
                int idx = tid + j * 512;
                int plane = idx / (BN * 8), cid = idx % (BN * 8);
                int row = cid >> 3, c = cid & 7;
                uint32_t so = row * 128 + ((c ^ (row & 7)) << 4);
                size_t go = (size_t)row * GN + k0 + c * 8;
                cp16(sb + ASZ + plane * BSZ + so,
                     (plane ? g_Blo[SRC] : g_Bhi[SRC]) + go);
            }
        }
        cp_commit();
    };

    issue(0); issue(1); issue(2);

    #pragma unroll 1
    for (int kt = 0; kt < NT; kt++) {
        cp_wait<2>();
        __syncthreads();
        issue(kt + 3);            // refills slot (kt-1)&3, safe post-sync

        const uint32_t sb = sb0 + (kt & 3) * STAGE;
        #pragma unroll
        for (int ks = 0; ks < 4; ks++) {      // four k16 steps per BK=64
            const int kc = ks * 2;
            uint32_t af[4];
            {
                int row = wm * 16 + (lane & 15);
                int ch = (kc + (lane >> 4)) ^ (row & 7);
                ldsm4(af, sb + row * 128 + ch * 16);
            }
            uint32_t bf[2][NF][2];
            #pragma unroll
            for (int bt = 0; bt < NF / 2; bt++) {
                int row = n0c + bt * 16 + (lane & 7) + ((lane >> 4) << 3);
                int ch = (kc + ((lane >> 3) & 1)) ^ (row & 7);
                uint32_t ad = sb + ASZ + row * 128 + ch * 16;
                uint32_t t[4];
                ldsm4(t, ad);                  // hi plane
                bf[0][2 * bt][0] = t[0]; bf[0][2 * bt][1] = t[1];
                bf[0][2 * bt + 1][0] = t[2]; bf[0][2 * bt + 1][1] = t[3];
                ldsm4(t, ad + BSZ);            // lo plane
                bf[1][2 * bt][0] = t[0]; bf[1][2 * bt][1] = t[1];
                bf[1][2 * bt + 1][0] = t[2]; bf[1][2 * bt + 1][1] = t[3];
            }
            #pragma unroll
            for (int nf = 0; nf < NF; nf++) {
                mma_f16(accM[nf], af, bf[0][nf]);   // Ah*Bhi -> main chain
                mma_f16(accC[nf], af, bf[1][nf]);   // Ah*Blo -> corr chain
            }
        }
    }
    __syncthreads();   // all warps done with stage smem before reuse

    // ---- epilogue: h = [relu](dinv*(acc + Zs_row) + bias) ----
    const int gr = lane >> 2;
    const int gc = (lane & 3) * 2;

    if constexpr (NC == 0) {
        #pragma unroll
        for (int half = 0; half < 2; half++) {
            int row = m0 + wm * 16 + half * 8 + gr;
            float di = g_dinv[row];
            #pragma unroll
            for (int nf = 0; nf < NF; nf++) {
                int col = n0c + nf * 8 + gc;
                float a0 = accM[nf][half * 2 + 0] + accC[nf][half * 2 + 0];
                float a1 = accM[nf][half * 2 + 1] + accC[nf][half * 2 + 1];
                float2 z = *reinterpret_cast<const float2*>(&g_Zs[SRC][(size_t)row * BN + col]);
                float v0 = fmaf(di, a0 + z.x, bias[col]);
                float v1 = fmaf(di, a1 + z.y, bias[col + 1]);
                if (RELU) { v0 = fmaxf(v0, 0.f); v1 = fmaxf(v1, 0.f); }
                *reinterpret_cast<float2*>(&Out[(size_t)row * BN + col]) = make_float2(v0, v1);
            }
        }
    } else {
        // fused feat-GEMM: hT[col][row] in smem (pad 66), W in smem, then h@W
        float* hT = reinterpret_cast<float*>(smem);          // [BN][66]
        float* Wsm = hT + BN * 66;                           // [BN][NC]
        #pragma unroll
        for (int half = 0; half < 2; half++) {
            int rl = wm * 16 + half * 8 + gr;
            int row = m0 + rl;
            float di = g_dinv[row];
            #pragma unroll
            for (int nf = 0; nf < NF; nf++) {
                int col = n0c + nf * 8 + gc;
                float a0 = accM[nf][half * 2 + 0] + accC[nf][half * 2 + 0];
                float a1 = accM[nf][half * 2 + 1] + accC[nf][half * 2 + 1];
                float2 z = *reinterpret_cast<const float2*>(&g_Zs[SRC][(size_t)row * BN + col]);
                float v0 = fmaf(di, a0 + z.x, bias[col]);
                float v1 = fmaf(di, a1 + z.y, bias[col + 1]);
                if (RELU) { v0 = fmaxf(v0, 0.f); v1 = fmaxf(v1, 0.f); }
                hT[col * 66 + rl] = v0;
                hT[(col + 1) * 66 + rl] = v1;
            }
        }
        #pragma unroll
        for (int it = 0; it < BN * NC / 4 / 512; it++) {
            int idx = tid + it * 512;
            reinterpret_cast<float4*>(Wsm)[idx] =
                reinterpret_cast<const float4*>(Wn)[idx];
        }
        __syncthreads();

        constexpr int CW = NC / 16;
        const int tx = tid & 15, ty = tid >> 4;   // 2 rows/thread, CW cols
        float a2[2][CW];
        #pragma unroll
        for (int r = 0; r < 2; r++)
            #pragma unroll
            for (int c = 0; c < CW; c++) a2[r][c] = 0.f;
        #pragma unroll 4
        for (int k = 0; k < BN; k++) {
            float h0 = hT[k * 66 + 2 * ty];
            float h1 = hT[k * 66 + 2 * ty + 1];
            #pragma unroll
            for (int c = 0; c < CW; c++) {
                float w = Wsm[k * NC + c * 16 + tx];
                a2[0][c] = fmaf(h0, w, a2[0][c]);
                a2[1][c] = fmaf(h1, w, a2[1][c]);
            }
        }
        constexpr int DST = 1 - SRC;
        #pragma unroll
        for (int r = 0; r < 2; r++) {
            int row = m0 + 2 * ty + r;
            float di = g_dinv[row];
            #pragma unroll
            for (int c = 0; c < CW; c++) {
                int col = c * 16 + tx;
                float z = di * a2[r][c];
                g_Zs[DST][(size_t)row * NC + col] = z;
                __half h = __float2half_rn(z);
                __half l = __float2half_rn(z - __half2float(h));
                g_Bhi[DST][(size_t)col * GN + row] = h;
                g_Blo[DST][(size_t)col * GN + row] = l;
            }
        }
    }
}

// ---------------------------------------------------------------------------
// Launch: 3-layer GCN
// ---------------------------------------------------------------------------
extern "C" void kernel_launch(void* const* d_in, const int* in_sizes, int n_in,
                              void* d_out, int out_size) {
    const float* x   = (const float*)d_in[0];
    const float* adj = (const float*)d_in[1];
    const float* W0  = (const float*)d_in[2];
    const float* b0  = (const float*)d_in[3];
    const float* W1  = (const float*)d_in[4];
    const float* b1  = (const float*)d_in[5];
    const float* W2  = (const float*)d_in[6];
    const float* b2  = (const float*)d_in[7];
    float* out = (float*)d_out;

    // smem: max(mainloop 4 stages, fused epilogue hT + W)
    const int MAIN128 = 4 * (8192 + 2 * 128 * 64 * 2);           // 163840
    const int MAIN64  = 4 * (8192 + 2 * 64 * 64 * 2);            // 98304
    const int EPI1 = 128 * 66 * 4 + 128 * 128 * 4;               // 99328
    const int EPI2 = 128 * 66 * 4 + 128 * 64 * 4;                // 66560
    const int SM_L1 = (MAIN128 > EPI1) ? MAIN128 : EPI1;         // 163840
    const int SM_L2 = (MAIN128 > EPI2) ? MAIN128 : EPI2;         // 163840
    const int SM_L3 = MAIN64;                                    // 98304
    cudaFuncSetAttribute(spmm_hmma<128, 128, 0, true>,
                         cudaFuncAttributeMaxDynamicSharedMemorySize, SM_L1);
    cudaFuncSetAttribute(spmm_hmma<128, 64, 1, true>,
                         cudaFuncAttributeMaxDynamicSharedMemorySize, SM_L2);
    cudaFuncSetAttribute(spmm_hmma<64, 0, 0, false>,
                         cudaFuncAttributeMaxDynamicSharedMemorySize, SM_L3);

    convert_rowsum<<<GN, 256>>>(adj);

    // layer 0 feat: Zs1 = dinv ⊙ (x@W0)  -> buffer 0
    feat_gemm<64, 128><<<GN / 64, 256>>>(x, W0);

    // layer 1: h1 = relu(An@Zs1 + b0); fused: Zs2 = dinv ⊙ (h1@W1) -> buffer 1
    spmm_hmma<128, 128, 0, true><<<GN / 64, 512, SM_L1>>>(b0, W1, nullptr);

    // layer 2: h2 = relu(An@Zs2 + b1); fused: Zs3 = dinv ⊙ (h2@W2) -> buffer 0
    spmm_hmma<128, 64, 1, true><<<GN / 64, 512, SM_L2>>>(b1, W2, nullptr);

    // layer 3: out = An@Zs3 + b2
    spmm_hmma<64, 0, 0, false><<<GN / 64, 512, SM_L3>>>(b2, nullptr, out);
}

// round 8
// speedup vs baseline: 2.2028x; 1.5823x over previous
#include <cuda_runtime.h>
#include <cuda_fp16.h>
#include <cstdint>

#define GN 8192

// ---------------------------------------------------------------------------
// Device-global scratch (allocation-free per harness rules)
// ---------------------------------------------------------------------------
__device__ float g_dinv[GN];
__device__ __half g_adj_h[(size_t)GN * GN];           // fp16 adj, 128 MB
// double-buffered per layer (ping-pong): fp32 Zs + transposed fp16 plane [n][k]
__device__ float g_Zs[2][(size_t)GN * 128];
__device__ __half g_Bh[2][(size_t)128 * GN];

// ---------------------------------------------------------------------------
// PTX helpers (compute_103-safe: cp.async + ldmatrix + mma.sync only)
// ---------------------------------------------------------------------------
__device__ __forceinline__ uint32_t smem_u32(const void* p) {
    uint32_t a;
    asm("{ .reg .u64 t; cvta.to.shared.u64 t, %1; cvt.u32.u64 %0, t; }" : "=r"(a) : "l"(p));
    return a;
}
__device__ __forceinline__ void cp16(uint32_t dst, const void* src) {
    asm volatile("cp.async.cg.shared.global [%0], [%1], 16;" :: "r"(dst), "l"(src));
}
__device__ __forceinline__ void cp_commit() { asm volatile("cp.async.commit_group;" ::: "memory"); }
template<int N>
__device__ __forceinline__ void cp_wait() { asm volatile("cp.async.wait_group %0;" :: "n"(N) : "memory"); }

__device__ __forceinline__ void ldsm4(uint32_t* r, uint32_t addr) {
    asm volatile("ldmatrix.sync.aligned.m8n8.x4.shared.b16 {%0,%1,%2,%3}, [%4];"
                 : "=r"(r[0]), "=r"(r[1]), "=r"(r[2]), "=r"(r[3]) : "r"(addr));
}
__device__ __forceinline__ void mma_f16(float* d, const uint32_t* a, const uint32_t* b) {
    asm volatile("mma.sync.aligned.m16n8k16.row.col.f32.f16.f16.f32 "
                 "{%0,%1,%2,%3}, {%4,%5,%6,%7}, {%8,%9}, {%0,%1,%2,%3};"
                 : "+f"(d[0]), "+f"(d[1]), "+f"(d[2]), "+f"(d[3])
                 : "r"(a[0]), "r"(a[1]), "r"(a[2]), "r"(a[3]), "r"(b[0]), "r"(b[1]));
}

// ---------------------------------------------------------------------------
// Kernel 1: rowsum (fp32-exact) + fp32 -> fp16 convert of adj (fused one pass)
// ---------------------------------------------------------------------------
__global__ void __launch_bounds__(256) convert_rowsum(const float* __restrict__ adj) {
    int row = blockIdx.x;
    int tid = threadIdx.x;
    const float4* src = reinterpret_cast<const float4*>(adj + (size_t)row * GN);
    uint2* dst = reinterpret_cast<uint2*>(g_adj_h + (size_t)row * GN);
    float s = 0.f;
    for (int i = tid; i < GN / 4; i += 256) {
        float4 v = src[i];
        s += (v.x + v.y) + (v.z + v.w);
        __half2 p0 = __floats2half2_rn(v.x, v.y);
        __half2 p1 = __floats2half2_rn(v.z, v.w);
        uint2 u;
        u.x = *reinterpret_cast<uint32_t*>(&p0);
        u.y = *reinterpret_cast<uint32_t*>(&p1);
        dst[i] = u;
    }
    __shared__ float red[8];
    #pragma unroll
    for (int o = 16; o; o >>= 1) s += __shfl_down_sync(0xffffffffu, s, o);
    if ((tid & 31) == 0) red[tid >> 5] = s;
    __syncthreads();
    if (tid == 0) {
        float t = 0.f;
        #pragma unroll
        for (int w = 0; w < 8; w++) t += red[w];
        g_dinv[row] = rsqrtf(t + 1.0f);
    }
}

// ---------------------------------------------------------------------------
// Kernel 2 (layer 0 only): Zs = dinv ⊙ (x @ W0) -> buffer 0 (fp32 + fp16 plane)
// ---------------------------------------------------------------------------
template<int K, int NC>
__global__ void __launch_bounds__(256) feat_gemm(const float* __restrict__ Xin,
                                                 const float* __restrict__ W) {
    constexpr int CW = NC / 16;
    __shared__ float hs[64][K];
    __shared__ float ws[16][NC];
    int tid = threadIdx.x;
    int r0 = blockIdx.x * 64;
    int tx = tid & 15, ty = tid >> 4;

    {
        const float4* s4 = reinterpret_cast<const float4*>(Xin + (size_t)r0 * K);
        float4* d4 = reinterpret_cast<float4*>(&hs[0][0]);
        for (int i = tid; i < 64 * K / 4; i += 256) d4[i] = s4[i];
    }
    float acc[4][CW];
    #pragma unroll
    for (int r = 0; r < 4; r++)
        #pragma unroll
        for (int c = 0; c < CW; c++) acc[r][c] = 0.f;

    for (int kc = 0; kc < K / 16; kc++) {
        __syncthreads();
        {
            const float4* s4 = reinterpret_cast<const float4*>(W + kc * 16 * NC);
            float4* d4 = reinterpret_cast<float4*>(&ws[0][0]);
            for (int i = tid; i < 16 * NC / 4; i += 256) d4[i] = s4[i];
        }
        __syncthreads();
        #pragma unroll
        for (int k = 0; k < 16; k++) {
            float a0 = hs[ty * 4 + 0][kc * 16 + k];
            float a1 = hs[ty * 4 + 1][kc * 16 + k];
            float a2 = hs[ty * 4 + 2][kc * 16 + k];
            float a3 = hs[ty * 4 + 3][kc * 16 + k];
            #pragma unroll
            for (int c = 0; c < CW; c++) {
                float w = ws[k][c * 16 + tx];
                acc[0][c] = fmaf(a0, w, acc[0][c]);
                acc[1][c] = fmaf(a1, w, acc[1][c]);
                acc[2][c] = fmaf(a2, w, acc[2][c]);
                acc[3][c] = fmaf(a3, w, acc[3][c]);
            }
        }
    }
    #pragma unroll
    for (int r = 0; r < 4; r++) {
        int row = r0 + ty * 4 + r;
        float di = g_dinv[row];
        #pragma unroll
        for (int c = 0; c < CW; c++) {
            int col = c * 16 + tx;
            float z = di * acc[r][c];
            g_Zs[0][(size_t)row * NC + col] = z;
            g_Bh[0][(size_t)col * GN + row] = __float2half_rn(z);
        }
    }
}

// ---------------------------------------------------------------------------
// Kernel 3: single-pass fp16 HMMA SpMM + fused epilogue
//   h = [relu]( dinv[i]*( adj_h@Bh + Zs[i,:] ) + bias )
//   If NC>0: also computes next layer's Zs = dinv ⊙ (h @ W) in-kernel.
//   BM=64 (128 CTAs), 512 threads = 16 warps:
//     8 warp positions (2m x 4n), each a 32x32 (BN=128) / 32x16 (BN=64) tile;
//     2-way K-split across warp groups (wg = warp>>3), reduced at the end.
//   BK=64, 4-stage cp.async. smem rows 128B, swizzle chunk' = c ^ (row & 7).
// ---------------------------------------------------------------------------
template<int BN, int NC, int SRC, bool RELU>
__global__ void __launch_bounds__(512) spmm_hmma(const float* __restrict__ bias,
                                                 const float* __restrict__ Wn,
                                                 float* __restrict__ Out) {
    constexpr int BK = 64;
    constexpr int NT = GN / BK;               // 128 k-tiles
    constexpr int ASZ = 64 * BK * 2;          // 8 KB fp16 A plane
    constexpr int BSZ = BN * BK * 2;          // fp16 B plane
    constexpr int STAGE = ASZ + BSZ;
    constexpr int WN = BN / 4;                // warp-position n extent (32 or 16)
    constexpr int NF = WN / 8;                // n8 fragments (4 or 2)
    constexpr int RB = 2 * NF * 4;            // accum floats per thread
    constexpr int EPIH = (NC > 0) ? (BN * 66 * 4 + BN * NC * 4) : 0;
    constexpr int MAINSZ = 4 * STAGE;
    constexpr int RBUF_OFF = (MAINSZ > EPIH) ? MAINSZ : EPIH;

    extern __shared__ char smem[];
    const uint32_t sb0 = smem_u32(smem);

    const int tid = threadIdx.x;
    const int lane = tid & 31;
    const int warp = tid >> 5;
    const int wg = warp >> 3;                 // k-split group 0/1
    const int wp = warp & 7;                  // warp position
    const int wm = wp >> 2;                   // 0..1 (32 rows each)
    const int wn = wp & 3;
    const int m0 = blockIdx.x * 64;
    const int n0c = wn * WN;

    float acc[2][NF][4];
    #pragma unroll
    for (int mt = 0; mt < 2; mt++)
        #pragma unroll
        for (int nf = 0; nf < NF; nf++)
            #pragma unroll
            for (int q = 0; q < 4; q++) acc[mt][nf][q] = 0.f;

    auto issue = [&](int kt) {
        if (kt < NT) {
            const uint32_t sb = sb0 + (kt & 3) * STAGE;
            const int k0 = kt * BK;
            {   // A: 64 rows x 8 chunks = 512 -> 1 chunk/thread
                int row = tid >> 3, c = tid & 7;
                uint32_t so = row * 128 + ((c ^ (row & 7)) << 4);
                cp16(sb + so, g_adj_h + (size_t)(m0 + row) * GN + k0 + c * 8);
            }
            #pragma unroll
            for (int j = 0; j < BN / 64; j++) {  // B: BN rows x 8 chunks
                int idx = tid + j * 512;
                int row = idx >> 3, c = idx & 7;
                uint32_t so = row * 128 + ((c ^ (row & 7)) << 4);
                cp16(sb + ASZ + so, g_Bh[SRC] + (size_t)row * GN + k0 + c * 8);
            }
        }
        cp_commit();
    };

    issue(0); issue(1); issue(2);

    #pragma unroll 1
    for (int kt = 0; kt < NT; kt++) {
        cp_wait<2>();
        __syncthreads();
        issue(kt + 3);            // refills slot (kt-1)&3, safe post-sync

        const uint32_t sb = sb0 + (kt & 3) * STAGE;
        #pragma unroll
        for (int s = 0; s < 2; s++) {          // this warp-group's k16 steps
            const int kc = (wg * 2 + s) * 2;   // base 16B-chunk
            uint32_t af[2][4];
            #pragma unroll
            for (int mt = 0; mt < 2; mt++) {
                int row = wm * 32 + mt * 16 + (lane & 15);
                int ch = (kc + (lane >> 4)) ^ (row & 7);
                ldsm4(af[mt], sb + row * 128 + ch * 16);
            }
            uint32_t bf[NF][2];
            #pragma unroll
            for (int bt = 0; bt < NF / 2; bt++) {
                int row = n0c + bt * 16 + (lane & 7) + ((lane >> 4) << 3);
                int ch = (kc + ((lane >> 3) & 1)) ^ (row & 7);
                uint32_t t[4];
                ldsm4(t, sb + ASZ + row * 128 + ch * 16);
                bf[2 * bt][0] = t[0]; bf[2 * bt][1] = t[1];
                bf[2 * bt + 1][0] = t[2]; bf[2 * bt + 1][1] = t[3];
            }
            #pragma unroll
            for (int mt = 0; mt < 2; mt++)
                #pragma unroll
                for (int nf = 0; nf < NF; nf++)
                    mma_f16(acc[mt][nf], af[mt], bf[nf]);
        }
    }

    // ---- K-split reduction: wg1 dumps accumulators, wg0 adds ----
    float* rbuf = reinterpret_cast<float*>(smem + RBUF_OFF);
    __syncthreads();
    if (wg == 1) {
        float* p = rbuf + (wp * 32 + lane) * (RB + 1);
        #pragma unroll
        for (int mt = 0; mt < 2; mt++)
            #pragma unroll
            for (int nf = 0; nf < NF; nf++)
                #pragma unroll
                for (int q = 0; q < 4; q++)
                    p[mt * NF * 4 + nf * 4 + q] = acc[mt][nf][q];
    }
    __syncthreads();
    if (wg == 0) {
        const float* p = rbuf + (wp * 32 + lane) * (RB + 1);
        #pragma unroll
        for (int mt = 0; mt < 2; mt++)
            #pragma unroll
            for (int nf = 0; nf < NF; nf++)
                #pragma unroll
                for (int q = 0; q < 4; q++)
                    acc[mt][nf][q] += p[mt * NF * 4 + nf * 4 + q];
    }
    __syncthreads();   // rbuf + stage smem free for reuse below

    // ---- epilogue: h = [relu](dinv*(acc + Zs_row) + bias) (wg0 warps hold sums)
    const int gr = lane >> 2;
    const int gc = (lane & 3) * 2;

    if constexpr (NC == 0) {
        if (wg == 0) {
            #pragma unroll
            for (int mt = 0; mt < 2; mt++)
                #pragma unroll
                for (int half = 0; half < 2; half++) {
                    int row = m0 + wm * 32 + mt * 16 + half * 8 + gr;
                    float di = g_dinv[row];
                    #pragma unroll
                    for (int nf = 0; nf < NF; nf++) {
                        int col = n0c + nf * 8 + gc;
                        float2 z = *reinterpret_cast<const float2*>(
                            &g_Zs[SRC][(size_t)row * BN + col]);
                        float v0 = fmaf(di, acc[mt][nf][half * 2 + 0] + z.x, bias[col]);
                        float v1 = fmaf(di, acc[mt][nf][half * 2 + 1] + z.y, bias[col + 1]);
                        if (RELU) { v0 = fmaxf(v0, 0.f); v1 = fmaxf(v1, 0.f); }
                        *reinterpret_cast<float2*>(&Out[(size_t)row * BN + col]) =
                            make_float2(v0, v1);
                    }
                }
        }
    } else {
        // fused feat-GEMM: hT[col][row] in smem (pad 66), W in smem, then h@W
        float* hT = reinterpret_cast<float*>(smem);          // [BN][66]
        float* Wsm = hT + BN * 66;                           // [BN][NC]
        if (wg == 0) {
            #pragma unroll
            for (int mt = 0; mt < 2; mt++)
                #pragma unroll
                for (int half = 0; half < 2; half++) {
                    int rl = wm * 32 + mt * 16 + half * 8 + gr;
                    int row = m0 + rl;
                    float di = g_dinv[row];
                    #pragma unroll
                    for (int nf = 0; nf < NF; nf++) {
                        int col = n0c + nf * 8 + gc;
                        float2 z = *reinterpret_cast<const float2*>(
                            &g_Zs[SRC][(size_t)row * BN + col]);
                        float v0 = fmaf(di, acc[mt][nf][half * 2 + 0] + z.x, bias[col]);
                        float v1 = fmaf(di, acc[mt][nf][half * 2 + 1] + z.y, bias[col + 1]);
                        if (RELU) { v0 = fmaxf(v0, 0.f); v1 = fmaxf(v1, 0.f); }
                        hT[col * 66 + rl] = v0;
                        hT[(col + 1) * 66 + rl] = v1;
                    }
                }
        }
        #pragma unroll
        for (int it = 0; it < BN * NC / 4 / 512; it++) {
            int idx = tid + it * 512;
            reinterpret_cast<float4*>(Wsm)[idx] =
                reinterpret_cast<const float4*>(Wn)[idx];
        }
        __syncthreads();

        constexpr int CW = NC / 16;
        const int tx = tid & 15, ty = tid >> 4;   // 2 rows/thread, CW cols
        float a2[2][CW];
        #pragma unroll
        for (int r = 0; r < 2; r++)
            #pragma unroll
            for (int c = 0; c < CW; c++) a2[r][c] = 0.f;
        #pragma unroll 4
        for (int k = 0; k < BN; k++) {
            float h0 = hT[k * 66 + 2 * ty];
            float h1 = hT[k * 66 + 2 * ty + 1];
            #pragma unroll
            for (int c = 0; c < CW; c++) {
                float w = Wsm[k * NC + c * 16 + tx];
                a2[0][c] = fmaf(h0, w, a2[0][c]);
                a2[1][c] = fmaf(h1, w, a2[1][c]);
            }
        }
        constexpr int DST = 1 - SRC;
        #pragma unroll
        for (int r = 0; r < 2; r++) {
            int row = m0 + 2 * ty + r;
            float di = g_dinv[row];
            #pragma unroll
            for (int c = 0; c < CW; c++) {
                int col = c * 16 + tx;
                float z = di * a2[r][c];
                g_Zs[DST][(size_t)row * NC + col] = z;
                g_Bh[DST][(size_t)col * GN + row] = __float2half_rn(z);
            }
        }
    }
}

// ---------------------------------------------------------------------------
// Launch: 3-layer GCN
// ---------------------------------------------------------------------------
extern "C" void kernel_launch(void* const* d_in, const int* in_sizes, int n_in,
                              void* d_out, int out_size) {
    const float* x   = (const float*)d_in[0];
    const float* adj = (const float*)d_in[1];
    const float* W0  = (const float*)d_in[2];
    const float* b0  = (const float*)d_in[3];
    const float* W1  = (const float*)d_in[4];
    const float* b1  = (const float*)d_in[5];
    const float* W2  = (const float*)d_in[6];
    const float* b2  = (const float*)d_in[7];
    float* out = (float*)d_out;

    // smem: max(4-stage mainloop, fused-epilogue hT+W) + reduction buffer
    const int MAIN128 = 4 * (8192 + 128 * 64 * 2);               // 98304
    const int MAIN64  = 4 * (8192 + 64 * 64 * 2);                // 65536
    const int EPI1 = 128 * 66 * 4 + 128 * 128 * 4;               // 99328
    const int EPI2 = 128 * 66 * 4 + 128 * 64 * 4;                // 66560
    const int RB128 = 8 * 32 * 33 * 4;                           // 33792
    const int RB64  = 8 * 32 * 17 * 4;                           // 17408
    const int SM_L1 = ((MAIN128 > EPI1) ? MAIN128 : EPI1) + RB128;  // 133120
    const int SM_L2 = ((MAIN128 > EPI2) ? MAIN128 : EPI2) + RB128;  // 132096
    const int SM_L3 = MAIN64 + RB64;                                // 82944
    cudaFuncSetAttribute(spmm_hmma<128, 128, 0, true>,
                         cudaFuncAttributeMaxDynamicSharedMemorySize, SM_L1);
    cudaFuncSetAttribute(spmm_hmma<128, 64, 1, true>,
                         cudaFuncAttributeMaxDynamicSharedMemorySize, SM_L2);
    cudaFuncSetAttribute(spmm_hmma<64, 0, 0, false>,
                         cudaFuncAttributeMaxDynamicSharedMemorySize, SM_L3);

    convert_rowsum<<<GN, 256>>>(adj);

    // layer 0 feat: Zs1 = dinv ⊙ (x@W0)  -> buffer 0
    feat_gemm<64, 128><<<GN / 64, 256>>>(x, W0);

    // layer 1: h1 = relu(An@Zs1 + b0); fused: Zs2 = dinv ⊙ (h1@W1) -> buffer 1
    spmm_hmma<128, 128, 0, true><<<GN / 64, 512, SM_L1>>>(b0, W1, nullptr);

    // layer 2: h2 = relu(An@Zs2 + b1); fused: Zs3 = dinv ⊙ (h2@W2) -> buffer 0
    spmm_hmma<128, 64, 1, true><<<GN / 64, 512, SM_L2>>>(b1, W2, nullptr);

    // layer 3: out = An@Zs3 + b2
    spmm_hmma<64, 0, 0, false><<<GN / 64, 512, SM_L3>>>(b2, nullptr, out);
}